// round 1
// baseline (speedup 1.0000x reference)
#include <cuda_runtime.h>
#include <cuda_bf16.h>

// Problem constants
#define BB 8
#define LQ 2048
#define LK 2048
#define DW 1024
#define DK 128
#define DV 128
#define INV_TEMP 0.08838834764831845f   // 1/sqrt(128)

// Scratch for projected qs/ks/vs  (8 MiB each, static device globals — no allocs)
__device__ float g_qs[BB * LQ * DK];
__device__ float g_ks[BB * LK * DK];
__device__ float g_vs[BB * LK * DV];

// ----------------------------------------------------------------------------
// Projection GEMM:  C[M=16384, 128] = A[M, 1024] * W[1024, 128]
// blockIdx.z selects q/k/v. BM=64, BN=128, BK=16, 256 threads, TM=8, TN=4.
// ----------------------------------------------------------------------------
__global__ __launch_bounds__(256) void proj_kernel(
    const float* __restrict__ q, const float* __restrict__ k,
    const float* __restrict__ v, const float* __restrict__ Wq,
    const float* __restrict__ Wk, const float* __restrict__ Wv)
{
    const float* A;
    const float* W;
    float* C;
    if (blockIdx.z == 0)      { A = q; W = Wq; C = g_qs; }
    else if (blockIdx.z == 1) { A = k; W = Wk; C = g_ks; }
    else                      { A = v; W = Wv; C = g_vs; }

    __shared__ float As[16][65];    // [k][m], padded
    __shared__ float Bs[16][128];   // [k][n]

    const int tid = threadIdx.x;
    const int tx = tid & 31;        // 0..31 -> col group (4 cols each)
    const int ty = tid >> 5;        // 0..7  -> row group (8 rows each)
    const int row0 = blockIdx.x * 64;

    // A-load mapping: one float4 per thread
    const int ar  = tid >> 2;       // 0..63
    const int ac4 = tid & 3;        // 0..3  (cols ac4*4 .. +3)

    float acc[8][4];
#pragma unroll
    for (int i = 0; i < 8; i++)
#pragma unroll
        for (int j = 0; j < 4; j++) acc[i][j] = 0.0f;

    for (int k0 = 0; k0 < DW; k0 += 16) {
        __syncthreads();
        // load A tile (64 x 16), store transposed
        float4 a4 = *(const float4*)&A[(size_t)(row0 + ar) * DW + k0 + ac4 * 4];
        As[ac4 * 4 + 0][ar] = a4.x;
        As[ac4 * 4 + 1][ar] = a4.y;
        As[ac4 * 4 + 2][ar] = a4.z;
        As[ac4 * 4 + 3][ar] = a4.w;
        // load B tile (16 x 128): two float4 per thread
#pragma unroll
        for (int it = 0; it < 2; it++) {
            int f4  = tid + it * 256;      // 0..511
            int br  = f4 >> 5;             // 0..15
            int bc4 = f4 & 31;             // 0..31
            float4 b4 = *(const float4*)&W[(size_t)(k0 + br) * DK + bc4 * 4];
            ((float4*)&Bs[br][0])[bc4] = b4;
        }
        __syncthreads();

#pragma unroll
        for (int kk = 0; kk < 16; kk++) {
            float a[8];
#pragma unroll
            for (int i = 0; i < 8; i++) a[i] = As[kk][ty * 8 + i];
            float4 b4 = ((const float4*)&Bs[kk][0])[tx];
#pragma unroll
            for (int i = 0; i < 8; i++) {
                acc[i][0] += a[i] * b4.x;
                acc[i][1] += a[i] * b4.y;
                acc[i][2] += a[i] * b4.z;
                acc[i][3] += a[i] * b4.w;
            }
        }
    }

#pragma unroll
    for (int i = 0; i < 8; i++) {
        float4 o;
        o.x = acc[i][0]; o.y = acc[i][1]; o.z = acc[i][2]; o.w = acc[i][3];
        *(float4*)&C[(size_t)(row0 + ty * 8 + i) * DK + tx * 4] = o;
    }
}

// ----------------------------------------------------------------------------
// Fused attention with online softmax over K-blocks of 64.
// Block = (64 q-rows, one batch). 256 threads; each thread owns an 8x4 tile
// of the [64 x 128] output accumulator. K-blocks fully past memory_length
// are skipped entirely.
// ----------------------------------------------------------------------------
#define SM_QS 0                         // 64*128 floats
#define SM_KS (64 * 128)                // 64*129 floats (padded)
#define SM_VS (SM_KS + 64 * 129)        // 64*128
#define SM_SS (SM_VS + 64 * 128)        // 64*65  (padded)
#define SM_M  (SM_SS + 64 * 65)         // 64
#define SM_L  (SM_M + 64)               // 64
#define SM_SC (SM_L + 64)               // 64
#define SMEM_FLOATS (SM_SC + 64)
#define SMEM_BYTES (SMEM_FLOATS * 4)

__global__ __launch_bounds__(256) void attn_kernel(
    const int* __restrict__ memory_lengths, float* __restrict__ out)
{
    extern __shared__ float sm[];
    float* Qs = sm + SM_QS;   // stride 128
    float* Ks = sm + SM_KS;   // stride 129
    float* Vs = sm + SM_VS;   // stride 128
    float* Ss = sm + SM_SS;   // stride 65
    float* m_s = sm + SM_M;
    float* l_s = sm + SM_L;
    float* sc_s = sm + SM_SC;

    const int tid = threadIdx.x;
    const int tx = tid & 31;
    const int ty = tid >> 5;
    const int b  = blockIdx.y;
    const int q0 = blockIdx.x * 64;
    const int memlen = memory_lengths[b];

    const float* Q = g_qs + (size_t)b * LQ * DK;
    const float* K = g_ks + (size_t)b * LK * DK;
    const float* V = g_vs + (size_t)b * LK * DV;

    // Load Q tile (64 x 128)
#pragma unroll
    for (int it = 0; it < 8; it++) {
        int f4 = tid + it * 256;           // 0..2047
        int qr = f4 >> 5, qc4 = f4 & 31;
        float4 qv = *(const float4*)&Q[(size_t)(q0 + qr) * DK + qc4 * 4];
        ((float4*)(Qs + qr * 128))[qc4] = qv;
    }
    if (tid < 64) { m_s[tid] = -1e30f; l_s[tid] = 0.0f; }

    float acc[8][4];
#pragma unroll
    for (int i = 0; i < 8; i++)
#pragma unroll
        for (int j = 0; j < 4; j++) acc[i][j] = 0.0f;

    const int nkb = (memlen + 63) >> 6;
    for (int kb = 0; kb < nkb; kb++) {
        const int kv0 = kb * 64;
        __syncthreads();
        // load K (padded stride 129) and V (stride 128) tiles
#pragma unroll
        for (int it = 0; it < 8; it++) {
            int f4 = tid + it * 256;
            int kr = f4 >> 5, kc4 = f4 & 31;
            float4 kv = *(const float4*)&K[(size_t)(kv0 + kr) * DK + kc4 * 4];
            Ks[kr * 129 + kc4 * 4 + 0] = kv.x;
            Ks[kr * 129 + kc4 * 4 + 1] = kv.y;
            Ks[kr * 129 + kc4 * 4 + 2] = kv.z;
            Ks[kr * 129 + kc4 * 4 + 3] = kv.w;
            float4 vv = *(const float4*)&V[(size_t)(kv0 + kr) * DV + kc4 * 4];
            ((float4*)(Vs + kr * 128))[kc4] = vv;
        }
        __syncthreads();

        // S = Q K^T * inv_temp ; each thread: 8 rows x 2 kcols
        float accs[8][2];
#pragma unroll
        for (int i = 0; i < 8; i++) { accs[i][0] = 0.0f; accs[i][1] = 0.0f; }
        const float* kr0 = Ks + (tx * 2 + 0) * 129;
        const float* kr1 = Ks + (tx * 2 + 1) * 129;
#pragma unroll 4
        for (int d = 0; d < 128; d++) {
            float k0v = kr0[d];
            float k1v = kr1[d];
#pragma unroll
            for (int i = 0; i < 8; i++) {
                float a = Qs[(ty * 8 + i) * 128 + d];
                accs[i][0] += a * k0v;
                accs[i][1] += a * k1v;
            }
        }
        const int gk0 = kv0 + tx * 2;
#pragma unroll
        for (int i = 0; i < 8; i++) {
#pragma unroll
            for (int jj = 0; jj < 2; jj++) {
                float s = (gk0 + jj < memlen) ? accs[i][jj] * INV_TEMP : -1e30f;
                Ss[(ty * 8 + i) * 65 + tx * 2 + jj] = s;
            }
        }
        __syncthreads();

        // Online-softmax row stats: one thread per q row
        if (tid < 64) {
            const int r = tid;
            float m_old = m_s[r];
            float mx = m_old;
#pragma unroll 4
            for (int c = 0; c < 64; c++) mx = fmaxf(mx, Ss[r * 65 + c]);
            float scale = __expf(m_old - mx);
            float sum = 0.0f;
#pragma unroll 4
            for (int c = 0; c < 64; c++) {
                float p = __expf(Ss[r * 65 + c] - mx);
                Ss[r * 65 + c] = p;
                sum += p;
            }
            l_s[r] = l_s[r] * scale + sum;
            m_s[r] = mx;
            sc_s[r] = scale;
        }
        __syncthreads();

        // rescale accumulator, then acc += P @ V
        float sc[8];
#pragma unroll
        for (int i = 0; i < 8; i++) sc[i] = sc_s[ty * 8 + i];
#pragma unroll
        for (int i = 0; i < 8; i++)
#pragma unroll
            for (int j = 0; j < 4; j++) acc[i][j] *= sc[i];

#pragma unroll 4
        for (int kk = 0; kk < 64; kk++) {
            float4 vv = ((const float4*)(Vs + kk * 128))[tx];
#pragma unroll
            for (int i = 0; i < 8; i++) {
                float p = Ss[(ty * 8 + i) * 65 + kk];
                acc[i][0] += p * vv.x;
                acc[i][1] += p * vv.y;
                acc[i][2] += p * vv.z;
                acc[i][3] += p * vv.w;
            }
        }
    }

    // normalize and write out
#pragma unroll
    for (int i = 0; i < 8; i++) {
        float rl = 1.0f / l_s[ty * 8 + i];
        float4 o;
        o.x = acc[i][0] * rl; o.y = acc[i][1] * rl;
        o.z = acc[i][2] * rl; o.w = acc[i][3] * rl;
        *(float4*)&out[(size_t)(b * LQ + q0 + ty * 8 + i) * DV + tx * 4] = o;
    }
}

// ----------------------------------------------------------------------------
extern "C" void kernel_launch(void* const* d_in, const int* in_sizes, int n_in,
                              void* d_out, int out_size)
{
    const float* q  = (const float*)d_in[0];
    const float* k  = (const float*)d_in[1];
    const float* v  = (const float*)d_in[2];
    const int* mlen = (const int*)d_in[3];
    const float* Wq = (const float*)d_in[4];
    const float* Wk = (const float*)d_in[5];
    const float* Wv = (const float*)d_in[6];
    float* out = (float*)d_out;

    // Phase 1: projections (q/k/v via blockIdx.z)
    dim3 pgrid(BB * LQ / 64, 1, 3);
    proj_kernel<<<pgrid, 256>>>(q, k, v, Wq, Wk, Wv);

    // Phase 2: fused masked attention
    cudaFuncSetAttribute(attn_kernel, cudaFuncAttributeMaxDynamicSharedMemorySize,
                         SMEM_BYTES);
    dim3 agrid(LQ / 64, BB);
    attn_kernel<<<agrid, 256, SMEM_BYTES>>>(mlen, out);
}

// round 3
// speedup vs baseline: 1.9597x; 1.9597x over previous
#include <cuda_runtime.h>
#include <cuda_bf16.h>
#include <cstdint>

// Problem constants
#define BB 8
#define LQ 2048
#define LK 2048
#define DW 1024
#define DKD 128
#define INV_TEMP 0.08838834764831845f   // 1/sqrt(128)

// Projected q/k/v scratch (static device globals — no allocs)
__device__ float g_qs[BB * LQ * DKD];
__device__ float g_ks[BB * LK * DKD];
__device__ float g_vs[BB * LK * DKD];

// ---------------------------------------------------------------------------
// tf32 helpers
// ---------------------------------------------------------------------------
__device__ __forceinline__ float to_tf32(float x) {
    uint32_t u;
    asm("cvt.rna.tf32.f32 %0, %1;" : "=r"(u) : "f"(x));
    return __uint_as_float(u);
}
__device__ __forceinline__ uint32_t fbits(float x) { return __float_as_uint(x); }

// mma.sync m16n8k8 tf32: D = A*B + D (A row-major, B col-major)
__device__ __forceinline__ void mma_tf32(float& c0, float& c1, float& c2, float& c3,
                                         uint32_t a0, uint32_t a1, uint32_t a2, uint32_t a3,
                                         uint32_t b0, uint32_t b1) {
    asm volatile(
        "mma.sync.aligned.m16n8k8.row.col.f32.tf32.tf32.f32 "
        "{%0,%1,%2,%3}, {%4,%5,%6,%7}, {%8,%9}, {%0,%1,%2,%3};"
        : "+f"(c0), "+f"(c1), "+f"(c2), "+f"(c3)
        : "r"(a0), "r"(a1), "r"(a2), "r"(a3), "r"(b0), "r"(b1));
}

// ---------------------------------------------------------------------------
// Projection GEMM via tf32 MMA:  C[16384,128] = A[16384,1024] * W[1024,128]
// Block tile: 128(M) x 128(N), BK=32. 256 threads = 8 warps.
// Warp tile: 32(M) x 64(N)  -> 2 m16 tiles x 8 n8 tiles.
// ---------------------------------------------------------------------------
__global__ __launch_bounds__(256) void proj_mma(
    const float* __restrict__ q, const float* __restrict__ k,
    const float* __restrict__ v, const float* __restrict__ Wq,
    const float* __restrict__ Wk, const float* __restrict__ Wv)
{
    const float* A; const float* W; float* C;
    if (blockIdx.z == 0)      { A = q; W = Wq; C = g_qs; }
    else if (blockIdx.z == 1) { A = k; W = Wk; C = g_ks; }
    else                      { A = v; W = Wv; C = g_vs; }

    __shared__ float As[128][36];   // [m][k], padded
    __shared__ float Ws[32][132];   // [k][n], padded

    const int tid  = threadIdx.x;
    const int lane = tid & 31;
    const int warp = tid >> 5;
    const int g    = lane >> 2;     // 0..7
    const int tig  = lane & 3;      // 0..3
    const int m0   = (warp & 3) * 32;
    const int n0   = (warp >> 2) * 64;
    const int row0 = blockIdx.x * 128;

    float acc[2][8][4];
#pragma unroll
    for (int mt = 0; mt < 2; mt++)
#pragma unroll
        for (int nt = 0; nt < 8; nt++)
#pragma unroll
            for (int c = 0; c < 4; c++) acc[mt][nt][c] = 0.0f;

    for (int k0 = 0; k0 < DW; k0 += 32) {
        __syncthreads();
        // A tile: 128x32 -> 1024 float4
#pragma unroll
        for (int it = 0; it < 4; it++) {
            int f4 = tid + it * 256;
            int r  = f4 >> 3, c4 = f4 & 7;
            float4 a4 = *(const float4*)&A[(size_t)(row0 + r) * DW + k0 + c4 * 4];
            As[r][c4 * 4 + 0] = to_tf32(a4.x);
            As[r][c4 * 4 + 1] = to_tf32(a4.y);
            As[r][c4 * 4 + 2] = to_tf32(a4.z);
            As[r][c4 * 4 + 3] = to_tf32(a4.w);
        }
        // W tile: 32x128 -> 1024 float4
#pragma unroll
        for (int it = 0; it < 4; it++) {
            int f4 = tid + it * 256;
            int r  = f4 >> 5, c4 = f4 & 31;
            float4 w4 = *(const float4*)&W[(size_t)(k0 + r) * DKD + c4 * 4];
            Ws[r][c4 * 4 + 0] = to_tf32(w4.x);
            Ws[r][c4 * 4 + 1] = to_tf32(w4.y);
            Ws[r][c4 * 4 + 2] = to_tf32(w4.z);
            Ws[r][c4 * 4 + 3] = to_tf32(w4.w);
        }
        __syncthreads();

#pragma unroll
        for (int kk = 0; kk < 32; kk += 8) {
            uint32_t a[2][4];
#pragma unroll
            for (int mt = 0; mt < 2; mt++) {
                int mr = m0 + mt * 16;
                a[mt][0] = fbits(As[mr + g][kk + tig]);
                a[mt][1] = fbits(As[mr + g + 8][kk + tig]);
                a[mt][2] = fbits(As[mr + g][kk + tig + 4]);
                a[mt][3] = fbits(As[mr + g + 8][kk + tig + 4]);
            }
#pragma unroll
            for (int nt = 0; nt < 8; nt++) {
                uint32_t b0 = fbits(Ws[kk + tig][n0 + nt * 8 + g]);
                uint32_t b1 = fbits(Ws[kk + tig + 4][n0 + nt * 8 + g]);
#pragma unroll
                for (int mt = 0; mt < 2; mt++)
                    mma_tf32(acc[mt][nt][0], acc[mt][nt][1], acc[mt][nt][2], acc[mt][nt][3],
                             a[mt][0], a[mt][1], a[mt][2], a[mt][3], b0, b1);
            }
        }
    }

    // Epilogue
#pragma unroll
    for (int mt = 0; mt < 2; mt++) {
        int r0 = row0 + m0 + mt * 16 + g;
#pragma unroll
        for (int nt = 0; nt < 8; nt++) {
            int col = n0 + nt * 8 + tig * 2;
            float2 o0 = make_float2(acc[mt][nt][0], acc[mt][nt][1]);
            float2 o1 = make_float2(acc[mt][nt][2], acc[mt][nt][3]);
            *(float2*)&C[(size_t)r0 * DKD + col]       = o0;
            *(float2*)&C[(size_t)(r0 + 8) * DKD + col] = o1;
        }
    }
}

// ---------------------------------------------------------------------------
// Fused flash attention via tf32 MMA. 64 q-rows per block, K-blocks of 64.
// 256 threads = 8 warps.
// S-phase warp tile: 16(q) x 32(kv);  PV-phase warp tile: 16(q) x 64(d).
// ---------------------------------------------------------------------------
#define QS_OFF 0
#define QS_ST  132
#define KS_OFF (QS_OFF + 64 * 132)       // 8448
#define KS_ST  132
#define VT_OFF (KS_OFF + 64 * 132)       // 16896
#define VT_ST  68
#define SS_OFF (VT_OFF + 128 * 68)       // 25600
#define SS_ST  72
#define MS_OFF (SS_OFF + 64 * 72)        // 30208
#define LS_OFF (MS_OFF + 64)
#define SC_OFF (LS_OFF + 64)
#define SMEMF  (SC_OFF + 64)             // 30400 floats
#define SMEMB  (SMEMF * 4)               // 121600 bytes

__global__ __launch_bounds__(256) void attn_mma(
    const int* __restrict__ memory_lengths, float* __restrict__ out)
{
    extern __shared__ float sm[];
    float* Qs = sm + QS_OFF;
    float* Ks = sm + KS_OFF;
    float* Vt = sm + VT_OFF;
    float* Ss = sm + SS_OFF;
    float* m_s  = sm + MS_OFF;
    float* l_s  = sm + LS_OFF;
    float* sc_s = sm + SC_OFF;

    const int tid  = threadIdx.x;
    const int lane = tid & 31;
    const int warp = tid >> 5;
    const int g    = lane >> 2;
    const int tig  = lane & 3;
    const int b    = blockIdx.y;
    const int q0   = blockIdx.x * 64;
    const int memlen = memory_lengths[b];

    // S-phase warp mapping
    const int sm0 = (warp & 3) * 16;
    const int sn0 = (warp >> 2) * 32;
    // PV-phase warp mapping
    const int pm0 = (warp & 3) * 16;
    const int pn0 = (warp >> 2) * 64;

    const float* Q = g_qs + (size_t)b * LQ * DKD;
    const float* K = g_ks + (size_t)b * LK * DKD;
    const float* V = g_vs + (size_t)b * LK * DKD;

    // Load Q tile (64 x 128), tf32-rounded
#pragma unroll
    for (int it = 0; it < 8; it++) {
        int f4 = tid + it * 256;
        int qr = f4 >> 5, qc4 = f4 & 31;
        float4 qv = *(const float4*)&Q[(size_t)(q0 + qr) * DKD + qc4 * 4];
        Qs[qr * QS_ST + qc4 * 4 + 0] = to_tf32(qv.x);
        Qs[qr * QS_ST + qc4 * 4 + 1] = to_tf32(qv.y);
        Qs[qr * QS_ST + qc4 * 4 + 2] = to_tf32(qv.z);
        Qs[qr * QS_ST + qc4 * 4 + 3] = to_tf32(qv.w);
    }
    if (tid < 64) { m_s[tid] = -1e30f; l_s[tid] = 0.0f; }

    float oacc[8][4];
#pragma unroll
    for (int nt = 0; nt < 8; nt++)
#pragma unroll
        for (int c = 0; c < 4; c++) oacc[nt][c] = 0.0f;

    const int nkb = (memlen + 63) >> 6;
    for (int kb = 0; kb < nkb; kb++) {
        const int kv0 = kb * 64;
        __syncthreads();
        // Load K (row-major tf32) and V (transposed tf32) tiles
#pragma unroll
        for (int it = 0; it < 8; it++) {
            int f4 = tid + it * 256;
            int kr = f4 >> 5, kc4 = f4 & 31;
            float4 kv = *(const float4*)&K[(size_t)(kv0 + kr) * DKD + kc4 * 4];
            Ks[kr * KS_ST + kc4 * 4 + 0] = to_tf32(kv.x);
            Ks[kr * KS_ST + kc4 * 4 + 1] = to_tf32(kv.y);
            Ks[kr * KS_ST + kc4 * 4 + 2] = to_tf32(kv.z);
            Ks[kr * KS_ST + kc4 * 4 + 3] = to_tf32(kv.w);
            float4 vv = *(const float4*)&V[(size_t)(kv0 + kr) * DKD + kc4 * 4];
            Vt[(kc4 * 4 + 0) * VT_ST + kr] = to_tf32(vv.x);
            Vt[(kc4 * 4 + 1) * VT_ST + kr] = to_tf32(vv.y);
            Vt[(kc4 * 4 + 2) * VT_ST + kr] = to_tf32(vv.z);
            Vt[(kc4 * 4 + 3) * VT_ST + kr] = to_tf32(vv.w);
        }
        __syncthreads();

        // ---- S = Q @ K^T  (raw, unscaled) ----
        float sacc[4][4];
#pragma unroll
        for (int nt = 0; nt < 4; nt++)
#pragma unroll
            for (int c = 0; c < 4; c++) sacc[nt][c] = 0.0f;

#pragma unroll
        for (int kk = 0; kk < 128; kk += 8) {
            uint32_t a0 = fbits(Qs[(sm0 + g) * QS_ST + kk + tig]);
            uint32_t a1 = fbits(Qs[(sm0 + g + 8) * QS_ST + kk + tig]);
            uint32_t a2 = fbits(Qs[(sm0 + g) * QS_ST + kk + tig + 4]);
            uint32_t a3 = fbits(Qs[(sm0 + g + 8) * QS_ST + kk + tig + 4]);
#pragma unroll
            for (int nt = 0; nt < 4; nt++) {
                uint32_t b0 = fbits(Ks[(sn0 + nt * 8 + g) * KS_ST + kk + tig]);
                uint32_t b1 = fbits(Ks[(sn0 + nt * 8 + g) * KS_ST + kk + tig + 4]);
                mma_tf32(sacc[nt][0], sacc[nt][1], sacc[nt][2], sacc[nt][3],
                         a0, a1, a2, a3, b0, b1);
            }
        }
        // store S to smem
#pragma unroll
        for (int nt = 0; nt < 4; nt++) {
            int col = sn0 + nt * 8 + tig * 2;
            Ss[(sm0 + g) * SS_ST + col]     = sacc[nt][0];
            Ss[(sm0 + g) * SS_ST + col + 1] = sacc[nt][1];
            Ss[(sm0 + g + 8) * SS_ST + col]     = sacc[nt][2];
            Ss[(sm0 + g + 8) * SS_ST + col + 1] = sacc[nt][3];
        }
        __syncthreads();

        // ---- online softmax: 4 threads per row, 16 cols each ----
        {
            const int r  = tid >> 2;
            const int qd = tid & 3;
            float m_old = m_s[r];
            float sv[16];
            float mx = m_old;
#pragma unroll
            for (int j = 0; j < 16; j++) {
                int c = qd * 16 + j;
                float s = Ss[r * SS_ST + c] * INV_TEMP;
                if (kv0 + c >= memlen) s = -1e30f;
                sv[j] = s;
                mx = fmaxf(mx, s);
            }
            mx = fmaxf(mx, __shfl_xor_sync(0xffffffff, mx, 1));
            mx = fmaxf(mx, __shfl_xor_sync(0xffffffff, mx, 2));
            float sum = 0.0f;
#pragma unroll
            for (int j = 0; j < 16; j++) {
                float p = __expf(sv[j] - mx);
                sum += p;
                Ss[r * SS_ST + qd * 16 + j] = to_tf32(p);
            }
            sum += __shfl_xor_sync(0xffffffff, sum, 1);
            sum += __shfl_xor_sync(0xffffffff, sum, 2);
            float scale = __expf(m_old - mx);
            if (qd == 0) {
                m_s[r] = mx;
                l_s[r] = l_s[r] * scale + sum;
                sc_s[r] = scale;
            }
        }
        __syncthreads();

        // ---- O = O*scale + P @ V ----
        float sc0 = sc_s[pm0 + g];
        float sc1 = sc_s[pm0 + g + 8];
#pragma unroll
        for (int nt = 0; nt < 8; nt++) {
            oacc[nt][0] *= sc0; oacc[nt][1] *= sc0;
            oacc[nt][2] *= sc1; oacc[nt][3] *= sc1;
        }
#pragma unroll
        for (int kk = 0; kk < 64; kk += 8) {
            uint32_t a0 = fbits(Ss[(pm0 + g) * SS_ST + kk + tig]);
            uint32_t a1 = fbits(Ss[(pm0 + g + 8) * SS_ST + kk + tig]);
            uint32_t a2 = fbits(Ss[(pm0 + g) * SS_ST + kk + tig + 4]);
            uint32_t a3 = fbits(Ss[(pm0 + g + 8) * SS_ST + kk + tig + 4]);
#pragma unroll
            for (int nt = 0; nt < 8; nt++) {
                uint32_t b0 = fbits(Vt[(pn0 + nt * 8 + g) * VT_ST + kk + tig]);
                uint32_t b1 = fbits(Vt[(pn0 + nt * 8 + g) * VT_ST + kk + tig + 4]);
                mma_tf32(oacc[nt][0], oacc[nt][1], oacc[nt][2], oacc[nt][3],
                         a0, a1, a2, a3, b0, b1);
            }
        }
    }

    // ---- normalize & write out ----
    float rl0 = 1.0f / l_s[pm0 + g];
    float rl1 = 1.0f / l_s[pm0 + g + 8];
#pragma unroll
    for (int nt = 0; nt < 8; nt++) {
        int col = pn0 + nt * 8 + tig * 2;
        int r0 = q0 + pm0 + g;
        float2 o0 = make_float2(oacc[nt][0] * rl0, oacc[nt][1] * rl0);
        float2 o1 = make_float2(oacc[nt][2] * rl1, oacc[nt][3] * rl1);
        *(float2*)&out[(size_t)(b * LQ + r0) * DKD + col]     = o0;
        *(float2*)&out[(size_t)(b * LQ + r0 + 8) * DKD + col] = o1;
    }
}

// ---------------------------------------------------------------------------
extern "C" void kernel_launch(void* const* d_in, const int* in_sizes, int n_in,
                              void* d_out, int out_size)
{
    const float* q  = (const float*)d_in[0];
    const float* k  = (const float*)d_in[1];
    const float* v  = (const float*)d_in[2];
    const int* mlen = (const int*)d_in[3];
    const float* Wq = (const float*)d_in[4];
    const float* Wk = (const float*)d_in[5];
    const float* Wv = (const float*)d_in[6];
    float* out = (float*)d_out;

    // Phase 1: projections
    dim3 pgrid(BB * LQ / 128, 1, 3);
    proj_mma<<<pgrid, 256>>>(q, k, v, Wq, Wk, Wv);

    // Phase 2: fused masked attention
    cudaFuncSetAttribute(attn_mma, cudaFuncAttributeMaxDynamicSharedMemorySize, SMEMB);
    dim3 agrid(LQ / 64, BB);
    attn_mma<<<agrid, 256, SMEMB>>>(mlen, out);
}

// round 4
// speedup vs baseline: 2.4437x; 1.2470x over previous
#include <cuda_runtime.h>
#include <cuda_bf16.h>
#include <cstdint>

// Problem constants
#define BB 8
#define LQ 2048
#define LK 2048
#define DW 1024
#define DKD 128
#define INV_TEMP 0.08838834764831845f   // 1/sqrt(128)

// Projected q/k/v scratch (static device globals — no allocs)
__device__ float g_qs[BB * LQ * DKD];
__device__ float g_ks[BB * LK * DKD];
__device__ float g_vs[BB * LK * DKD];

// ---------------------------------------------------------------------------
// helpers
// ---------------------------------------------------------------------------
__device__ __forceinline__ float to_tf32(float x) {
    uint32_t u;
    asm("cvt.rna.tf32.f32 %0, %1;" : "=r"(u) : "f"(x));
    return __uint_as_float(u);
}
__device__ __forceinline__ uint32_t tf32_bits(float x) {
    uint32_t u;
    asm("cvt.rna.tf32.f32 %0, %1;" : "=r"(u) : "f"(x));
    return u;
}
__device__ __forceinline__ uint32_t fbits(float x) { return __float_as_uint(x); }

// mma.sync m16n8k8 tf32: D = A*B + D (A row-major, B col-major)
__device__ __forceinline__ void mma_tf32(float& c0, float& c1, float& c2, float& c3,
                                         uint32_t a0, uint32_t a1, uint32_t a2, uint32_t a3,
                                         uint32_t b0, uint32_t b1) {
    asm volatile(
        "mma.sync.aligned.m16n8k8.row.col.f32.tf32.tf32.f32 "
        "{%0,%1,%2,%3}, {%4,%5,%6,%7}, {%8,%9}, {%0,%1,%2,%3};"
        : "+f"(c0), "+f"(c1), "+f"(c2), "+f"(c3)
        : "r"(a0), "r"(a1), "r"(a2), "r"(a3), "r"(b0), "r"(b1));
}

__device__ __forceinline__ void cp16(uint32_t saddr, const void* gaddr) {
    asm volatile("cp.async.ca.shared.global [%0], [%1], 16;" :: "r"(saddr), "l"(gaddr));
}

// ---------------------------------------------------------------------------
// Projection GEMM via tf32 MMA + cp.async double buffering.
// C[16384,128] = A[16384,1024] * W[1024,128]
// Block: 128(M) x 128(N), BK=32, 256 threads = 8 warps, warp tile 32x64.
// smem holds RAW fp32; tf32 rounding applied at fragment-load time
// (numerically identical to rounding at store time).
// ---------------------------------------------------------------------------
#define PJ_AS0 0                      // 128*36
#define PJ_AS1 (PJ_AS0 + 128 * 36)   // 4608
#define PJ_WS0 (PJ_AS1 + 128 * 36)   // 9216  (32*132)
#define PJ_WS1 (PJ_WS0 + 32 * 132)   // 13440
#define PJ_SMF (PJ_WS1 + 32 * 132)   // 17664 floats
#define PJ_SMB (PJ_SMF * 4)          // 70656 bytes

__global__ __launch_bounds__(256) void proj_mma(
    const float* __restrict__ q, const float* __restrict__ k,
    const float* __restrict__ v, const float* __restrict__ Wq,
    const float* __restrict__ Wk, const float* __restrict__ Wv)
{
    const float* A; const float* W; float* C;
    if (blockIdx.z == 0)      { A = q; W = Wq; C = g_qs; }
    else if (blockIdx.z == 1) { A = k; W = Wk; C = g_ks; }
    else                      { A = v; W = Wv; C = g_vs; }

    extern __shared__ float psm[];
    const uint32_t sbase = (uint32_t)__cvta_generic_to_shared(psm);

    const int tid  = threadIdx.x;
    const int lane = tid & 31;
    const int warp = tid >> 5;
    const int g    = lane >> 2;
    const int tig  = lane & 3;
    const int m0   = (warp & 3) * 32;
    const int n0   = (warp >> 2) * 64;
    const int row0 = blockIdx.x * 128;

    float acc[2][8][4];
#pragma unroll
    for (int mt = 0; mt < 2; mt++)
#pragma unroll
        for (int nt = 0; nt < 8; nt++)
#pragma unroll
            for (int c = 0; c < 4; c++) acc[mt][nt][c] = 0.0f;

    // tile issue: A 128x32 (1024 f4), W 32x128 (1024 f4); 4 cp.async each per thread
    auto issue_tiles = [&](int buf, int k0) {
        const int aoff = buf ? PJ_AS1 : PJ_AS0;
        const int woff = buf ? PJ_WS1 : PJ_WS0;
#pragma unroll
        for (int it = 0; it < 4; it++) {
            int f4 = tid + it * 256;
            int r  = f4 >> 3, c4 = f4 & 7;
            cp16(sbase + (uint32_t)(aoff + r * 36 + c4 * 4) * 4,
                 &A[(size_t)(row0 + r) * DW + k0 + c4 * 4]);
        }
#pragma unroll
        for (int it = 0; it < 4; it++) {
            int f4 = tid + it * 256;
            int r  = f4 >> 5, c4 = f4 & 31;
            cp16(sbase + (uint32_t)(woff + r * 132 + c4 * 4) * 4,
                 &W[(size_t)(k0 + r) * DKD + c4 * 4]);
        }
    };

    issue_tiles(0, 0);
    asm volatile("cp.async.commit_group;");

    for (int i = 0; i < 32; i++) {
        const int buf = i & 1;
        if (i + 1 < 32) {
            issue_tiles(1 - buf, (i + 1) * 32);
            asm volatile("cp.async.commit_group;");
            asm volatile("cp.async.wait_group 1;");
        } else {
            asm volatile("cp.async.wait_group 0;");
        }
        __syncthreads();

        const float* As = psm + (buf ? PJ_AS1 : PJ_AS0);
        const float* Ws = psm + (buf ? PJ_WS1 : PJ_WS0);

#pragma unroll
        for (int kk = 0; kk < 32; kk += 8) {
            uint32_t a[2][4];
#pragma unroll
            for (int mt = 0; mt < 2; mt++) {
                int mr = m0 + mt * 16;
                a[mt][0] = tf32_bits(As[(mr + g) * 36 + kk + tig]);
                a[mt][1] = tf32_bits(As[(mr + g + 8) * 36 + kk + tig]);
                a[mt][2] = tf32_bits(As[(mr + g) * 36 + kk + tig + 4]);
                a[mt][3] = tf32_bits(As[(mr + g + 8) * 36 + kk + tig + 4]);
            }
#pragma unroll
            for (int nt = 0; nt < 8; nt++) {
                uint32_t b0 = tf32_bits(Ws[(kk + tig) * 132 + n0 + nt * 8 + g]);
                uint32_t b1 = tf32_bits(Ws[(kk + tig + 4) * 132 + n0 + nt * 8 + g]);
#pragma unroll
                for (int mt = 0; mt < 2; mt++)
                    mma_tf32(acc[mt][nt][0], acc[mt][nt][1], acc[mt][nt][2], acc[mt][nt][3],
                             a[mt][0], a[mt][1], a[mt][2], a[mt][3], b0, b1);
            }
        }
        __syncthreads();
    }

    // Epilogue
#pragma unroll
    for (int mt = 0; mt < 2; mt++) {
        int r0 = row0 + m0 + mt * 16 + g;
#pragma unroll
        for (int nt = 0; nt < 8; nt++) {
            int col = n0 + nt * 8 + tig * 2;
            float2 o0 = make_float2(acc[mt][nt][0], acc[mt][nt][1]);
            float2 o1 = make_float2(acc[mt][nt][2], acc[mt][nt][3]);
            *(float2*)&C[(size_t)r0 * DKD + col]       = o0;
            *(float2*)&C[(size_t)(r0 + 8) * DKD + col] = o1;
        }
    }
}

// ---------------------------------------------------------------------------
// Fused flash attention via tf32 MMA. 64 q-rows per block, K-blocks of 64.
// 512 threads = 16 warps.
//  S-phase warp tile: 16(q) x 16(kv)   (4 q-warps x 4 kv-warps)
//  PV-phase warp tile: 16(q) x 32(d)   (4 q-warps x 4 d-warps)
// V kept ROW-MAJOR in smem; B fragments for PV read V[kv][d] directly
// (conflict-free: banks = 4*tig + g). No transpose, no conflicted stores.
// Next K/V tile prefetched into registers during compute.
// ---------------------------------------------------------------------------
#define QS_OFF 0
#define TILE_ST 132
#define KS_OFF (QS_OFF + 64 * 132)       // 8448
#define VS_OFF (KS_OFF + 64 * 132)       // 16896
#define SS_OFF (VS_OFF + 64 * 132)       // 25344
#define SS_ST  68
#define MS_OFF (SS_OFF + 64 * 68)        // 29696
#define LS_OFF (MS_OFF + 64)
#define SC_OFF (LS_OFF + 64)
#define SMEMF  (SC_OFF + 64)             // 29888 floats
#define SMEMB  (SMEMF * 4)               // 119552 bytes

__global__ __launch_bounds__(512) void attn_mma(
    const int* __restrict__ memory_lengths, float* __restrict__ out)
{
    extern __shared__ float sm[];
    float* Qs = sm + QS_OFF;
    float* Ks = sm + KS_OFF;
    float* Vs = sm + VS_OFF;
    float* Ss = sm + SS_OFF;
    float* m_s  = sm + MS_OFF;
    float* l_s  = sm + LS_OFF;
    float* sc_s = sm + SC_OFF;

    const int tid  = threadIdx.x;
    const int lane = tid & 31;
    const int warp = tid >> 5;
    const int g    = lane >> 2;
    const int tig  = lane & 3;
    const int b    = blockIdx.y;
    const int q0   = blockIdx.x * 64;
    const int memlen = memory_lengths[b];

    const int sm0 = (warp & 3) * 16;    // q-rows for this warp (both phases)
    const int sn0 = (warp >> 2) * 16;   // kv cols (S-phase)
    const int pn0 = (warp >> 2) * 32;   // d cols (PV-phase)

    const float* Q = g_qs + (size_t)b * LQ * DKD;
    const float* K = g_ks + (size_t)b * LK * DKD;
    const float* V = g_vs + (size_t)b * LK * DKD;

    // Load Q tile (64 x 128): 2048 float4 over 512 threads
#pragma unroll
    for (int it = 0; it < 4; it++) {
        int f4 = tid + it * 512;
        int qr = f4 >> 5, qc4 = f4 & 31;
        float4 qv = *(const float4*)&Q[(size_t)(q0 + qr) * DKD + qc4 * 4];
        Qs[qr * TILE_ST + qc4 * 4 + 0] = to_tf32(qv.x);
        Qs[qr * TILE_ST + qc4 * 4 + 1] = to_tf32(qv.y);
        Qs[qr * TILE_ST + qc4 * 4 + 2] = to_tf32(qv.z);
        Qs[qr * TILE_ST + qc4 * 4 + 3] = to_tf32(qv.w);
    }
    if (tid < 64) { m_s[tid] = -1e30f; l_s[tid] = 0.0f; }

    float oacc[4][4];
#pragma unroll
    for (int nt = 0; nt < 4; nt++)
#pragma unroll
        for (int c = 0; c < 4; c++) oacc[nt][c] = 0.0f;

    const int nkb = (memlen + 63) >> 6;

    // Prefetch K/V block 0 into registers
    float4 kpre[4], vpre[4];
#pragma unroll
    for (int it = 0; it < 4; it++) {
        int f4 = tid + it * 512;
        int kr = f4 >> 5, kc4 = f4 & 31;
        kpre[it] = *(const float4*)&K[(size_t)kr * DKD + kc4 * 4];
        vpre[it] = *(const float4*)&V[(size_t)kr * DKD + kc4 * 4];
    }

    for (int kb = 0; kb < nkb; kb++) {
        const int kv0 = kb * 64;
        __syncthreads();    // previous iteration's smem reads complete
        // Store prefetched K/V tiles (tf32-rounded), both row-major
#pragma unroll
        for (int it = 0; it < 4; it++) {
            int f4 = tid + it * 512;
            int kr = f4 >> 5, kc4 = f4 & 31;
            float* kd = Ks + kr * TILE_ST + kc4 * 4;
            kd[0] = to_tf32(kpre[it].x); kd[1] = to_tf32(kpre[it].y);
            kd[2] = to_tf32(kpre[it].z); kd[3] = to_tf32(kpre[it].w);
            float* vd = Vs + kr * TILE_ST + kc4 * 4;
            vd[0] = to_tf32(vpre[it].x); vd[1] = to_tf32(vpre[it].y);
            vd[2] = to_tf32(vpre[it].z); vd[3] = to_tf32(vpre[it].w);
        }
        // Kick off prefetch of next block (hidden under compute below)
        if (kb + 1 < nkb) {
            const int nv0 = kv0 + 64;
#pragma unroll
            for (int it = 0; it < 4; it++) {
                int f4 = tid + it * 512;
                int kr = f4 >> 5, kc4 = f4 & 31;
                kpre[it] = *(const float4*)&K[(size_t)(nv0 + kr) * DKD + kc4 * 4];
                vpre[it] = *(const float4*)&V[(size_t)(nv0 + kr) * DKD + kc4 * 4];
            }
        }
        __syncthreads();

        // ---- S = Q @ K^T (warp tile 16x16) ----
        float sacc[2][4];
#pragma unroll
        for (int nt = 0; nt < 2; nt++)
#pragma unroll
            for (int c = 0; c < 4; c++) sacc[nt][c] = 0.0f;

#pragma unroll
        for (int kk = 0; kk < 128; kk += 8) {
            uint32_t a0 = fbits(Qs[(sm0 + g) * TILE_ST + kk + tig]);
            uint32_t a1 = fbits(Qs[(sm0 + g + 8) * TILE_ST + kk + tig]);
            uint32_t a2 = fbits(Qs[(sm0 + g) * TILE_ST + kk + tig + 4]);
            uint32_t a3 = fbits(Qs[(sm0 + g + 8) * TILE_ST + kk + tig + 4]);
#pragma unroll
            for (int nt = 0; nt < 2; nt++) {
                uint32_t b0 = fbits(Ks[(sn0 + nt * 8 + g) * TILE_ST + kk + tig]);
                uint32_t b1 = fbits(Ks[(sn0 + nt * 8 + g) * TILE_ST + kk + tig + 4]);
                mma_tf32(sacc[nt][0], sacc[nt][1], sacc[nt][2], sacc[nt][3],
                         a0, a1, a2, a3, b0, b1);
            }
        }
#pragma unroll
        for (int nt = 0; nt < 2; nt++) {
            int col = sn0 + nt * 8 + tig * 2;
            Ss[(sm0 + g) * SS_ST + col]         = sacc[nt][0];
            Ss[(sm0 + g) * SS_ST + col + 1]     = sacc[nt][1];
            Ss[(sm0 + g + 8) * SS_ST + col]     = sacc[nt][2];
            Ss[(sm0 + g + 8) * SS_ST + col + 1] = sacc[nt][3];
        }
        __syncthreads();

        // ---- online softmax: 8 threads per row, 8 cols each ----
        {
            const int r  = tid >> 3;
            const int q8 = tid & 7;
            float m_old = m_s[r];
            float sv[8];
            float mx = m_old;
#pragma unroll
            for (int j = 0; j < 8; j++) {
                int c = q8 * 8 + j;
                float s = Ss[r * SS_ST + c] * INV_TEMP;
                if (kv0 + c >= memlen) s = -1e30f;
                sv[j] = s;
                mx = fmaxf(mx, s);
            }
            mx = fmaxf(mx, __shfl_xor_sync(0xffffffff, mx, 1));
            mx = fmaxf(mx, __shfl_xor_sync(0xffffffff, mx, 2));
            mx = fmaxf(mx, __shfl_xor_sync(0xffffffff, mx, 4));
            float sum = 0.0f;
#pragma unroll
            for (int j = 0; j < 8; j++) {
                float p = __expf(sv[j] - mx);
                sum += p;
                Ss[r * SS_ST + q8 * 8 + j] = to_tf32(p);
            }
            sum += __shfl_xor_sync(0xffffffff, sum, 1);
            sum += __shfl_xor_sync(0xffffffff, sum, 2);
            sum += __shfl_xor_sync(0xffffffff, sum, 4);
            float scale = __expf(m_old - mx);
            if (q8 == 0) {
                m_s[r] = mx;
                l_s[r] = l_s[r] * scale + sum;
                sc_s[r] = scale;
            }
        }
        __syncthreads();

        // ---- O = O*scale + P @ V  (warp tile 16x32) ----
        float sc0 = sc_s[sm0 + g];
        float sc1 = sc_s[sm0 + g + 8];
#pragma unroll
        for (int nt = 0; nt < 4; nt++) {
            oacc[nt][0] *= sc0; oacc[nt][1] *= sc0;
            oacc[nt][2] *= sc1; oacc[nt][3] *= sc1;
        }
#pragma unroll
        for (int kk = 0; kk < 64; kk += 8) {
            uint32_t a0 = fbits(Ss[(sm0 + g) * SS_ST + kk + tig]);
            uint32_t a1 = fbits(Ss[(sm0 + g + 8) * SS_ST + kk + tig]);
            uint32_t a2 = fbits(Ss[(sm0 + g) * SS_ST + kk + tig + 4]);
            uint32_t a3 = fbits(Ss[(sm0 + g + 8) * SS_ST + kk + tig + 4]);
#pragma unroll
            for (int nt = 0; nt < 4; nt++) {
                // B(k=kv, n=d) = V[kv][d] — row-major V, conflict-free
                uint32_t b0 = fbits(Vs[(kk + tig) * TILE_ST + pn0 + nt * 8 + g]);
                uint32_t b1 = fbits(Vs[(kk + tig + 4) * TILE_ST + pn0 + nt * 8 + g]);
                mma_tf32(oacc[nt][0], oacc[nt][1], oacc[nt][2], oacc[nt][3],
                         a0, a1, a2, a3, b0, b1);
            }
        }
    }

    // ---- normalize & write out ----
    float rl0 = 1.0f / l_s[sm0 + g];
    float rl1 = 1.0f / l_s[sm0 + g + 8];
#pragma unroll
    for (int nt = 0; nt < 4; nt++) {
        int col = pn0 + nt * 8 + tig * 2;
        int r0 = q0 + sm0 + g;
        float2 o0 = make_float2(oacc[nt][0] * rl0, oacc[nt][1] * rl0);
        float2 o1 = make_float2(oacc[nt][2] * rl1, oacc[nt][3] * rl1);
        *(float2*)&out[(size_t)(b * LQ + r0) * DKD + col]     = o0;
        *(float2*)&out[(size_t)(b * LQ + r0 + 8) * DKD + col] = o1;
    }
}

// ---------------------------------------------------------------------------
extern "C" void kernel_launch(void* const* d_in, const int* in_sizes, int n_in,
                              void* d_out, int out_size)
{
    const float* q  = (const float*)d_in[0];
    const float* k  = (const float*)d_in[1];
    const float* v  = (const float*)d_in[2];
    const int* mlen = (const int*)d_in[3];
    const float* Wq = (const float*)d_in[4];
    const float* Wk = (const float*)d_in[5];
    const float* Wv = (const float*)d_in[6];
    float* out = (float*)d_out;

    // Phase 1: projections (double-buffered tf32 MMA)
    cudaFuncSetAttribute(proj_mma, cudaFuncAttributeMaxDynamicSharedMemorySize, PJ_SMB);
    dim3 pgrid(BB * LQ / 128, 1, 3);
    proj_mma<<<pgrid, 256, PJ_SMB>>>(q, k, v, Wq, Wk, Wv);

    // Phase 2: fused masked attention (512 threads, register prefetch)
    cudaFuncSetAttribute(attn_mma, cudaFuncAttributeMaxDynamicSharedMemorySize, SMEMB);
    dim3 agrid(LQ / 64, BB);
    attn_mma<<<agrid, 512, SMEMB>>>(mlen, out);
}